// round 1
// baseline (speedup 1.0000x reference)
#include <cuda_runtime.h>

// ---------------- problem constants ----------------
#define BATCH   2
#define SEQ     2048
#define DMODEL  512
#define NHEADS  8
#define DH      64
#define MROWS   (BATCH*SEQ)      // 4096
#define THREE_D (3*DMODEL)       // 1536

// scratch (no cudaMalloc allowed)
__device__ float g_qkv[(size_t)MROWS * THREE_D];   // 25.2 MB
__device__ float g_att[(size_t)MROWS * DMODEL];    //  8.4 MB

// ---------------------------------------------------------------------------
// GEMM: C[M,N] = A[M,K] @ B[N,K]^T + bias[N]
// A, B row-major with K contiguous (NT gemm). 128x128x16 tile, 8x8/thread.
// ---------------------------------------------------------------------------
__global__ __launch_bounds__(256)
void gemm_nt_bias(const float* __restrict__ A, const float* __restrict__ B,
                  const float* __restrict__ bias, float* __restrict__ C,
                  int M, int N, int K)
{
    __shared__ float As[16][132];   // transposed: As[k][m], pad keeps 16B align (132*4=528, 528%16==0)
    __shared__ float Bs[16][132];

    const int tid = threadIdx.x;
    const int ty  = tid >> 4;
    const int tx  = tid & 15;
    const int bm  = blockIdx.y * 128;
    const int bn  = blockIdx.x * 128;

    const float* Ab = A + (size_t)bm * K;
    const float* Bb = B + (size_t)bn * K;

    float acc[8][8] = {};

    for (int k0 = 0; k0 < K; k0 += 16) {
        #pragma unroll
        for (int t = 0; t < 2; t++) {
            int idx = tid + t * 256;           // 0..511
            int row = idx >> 2;                // 0..127
            int kq  = (idx & 3) << 2;          // 0,4,8,12
            float4 va = *(const float4*)(Ab + (size_t)row * K + k0 + kq);
            As[kq+0][row] = va.x; As[kq+1][row] = va.y;
            As[kq+2][row] = va.z; As[kq+3][row] = va.w;
            float4 vb = *(const float4*)(Bb + (size_t)row * K + k0 + kq);
            Bs[kq+0][row] = vb.x; Bs[kq+1][row] = vb.y;
            Bs[kq+2][row] = vb.z; Bs[kq+3][row] = vb.w;
        }
        __syncthreads();

        #pragma unroll
        for (int kk = 0; kk < 16; kk++) {
            float a[8], b[8];
            *(float4*)&a[0] = *(const float4*)&As[kk][ty * 4];
            *(float4*)&a[4] = *(const float4*)&As[kk][64 + ty * 4];
            *(float4*)&b[0] = *(const float4*)&Bs[kk][tx * 4];
            *(float4*)&b[4] = *(const float4*)&Bs[kk][64 + tx * 4];
            #pragma unroll
            for (int i = 0; i < 8; i++)
                #pragma unroll
                for (int j = 0; j < 8; j++)
                    acc[i][j] += a[i] * b[j];
        }
        __syncthreads();
    }

    float4 blo = *(const float4*)(bias + bn + tx * 4);
    float4 bhi = *(const float4*)(bias + bn + 64 + tx * 4);
    #pragma unroll
    for (int i = 0; i < 8; i++) {
        int row = bm + ((i < 4) ? (ty * 4 + i) : (60 + ty * 4 + i));
        float* Cr = C + (size_t)row * N;
        float4 lo = make_float4(acc[i][0] + blo.x, acc[i][1] + blo.y,
                                acc[i][2] + blo.z, acc[i][3] + blo.w);
        float4 hi = make_float4(acc[i][4] + bhi.x, acc[i][5] + bhi.y,
                                acc[i][6] + bhi.z, acc[i][7] + bhi.w);
        *(float4*)(Cr + bn + tx * 4)      = lo;
        *(float4*)(Cr + bn + 64 + tx * 4) = hi;
    }
}

// ---------------------------------------------------------------------------
// Flash attention (fp32, online softmax, causal).
// qkv: [4096, 1536] with chunk order q | v | k (reference quirk).
// Grid: (S/64 q-tiles, B*H). 256 threads, 4x4 per thread.
// Shared: Qs(16K) + KP(16K, K swizzled then reused for P) + Vs(16K) = 48K static.
// ---------------------------------------------------------------------------
__global__ __launch_bounds__(256)
void flash_attn_kernel(const float* __restrict__ qkv,
                       const int*   __restrict__ cmask,
                       float* __restrict__ Out)
{
    __shared__ float Qs[64 * 64];
    __shared__ float KP[64 * 64];   // K tile (swizzled), reused for P tile
    __shared__ float Vs[64 * 64];

    const int tid = threadIdx.x;
    const int ty  = tid >> 4;
    const int tx  = tid & 15;
    const int qt  = blockIdx.x;
    const int bh  = blockIdx.y;
    const int b   = bh >> 3;
    const int h   = bh & 7;
    const int causal = cmask[0];
    const float scale = 0.125f;     // 1/sqrt(64)

    const float* base = qkv + (size_t)(b * SEQ) * THREE_D + h * DH;
    const float* Qg = base;               // q chunk (offset 0)
    const float* Vg = base + DMODEL;      // v chunk (offset 512)  <- q,v,k order!
    const float* Kg = base + 2 * DMODEL;  // k chunk (offset 1024)

    // load Q tile
    {
        const int q0 = qt * 64;
        #pragma unroll
        for (int t = 0; t < 4; t++) {
            int idx = tid + t * 256;
            int r   = idx >> 4;
            int d4  = idx & 15;
            float4 v = *(const float4*)(Qg + (size_t)(q0 + r) * THREE_D + d4 * 4);
            *(float4*)&Qs[r * 64 + d4 * 4] = v;
        }
    }

    float o[4][4] = {};
    float m[4] = {-1e30f, -1e30f, -1e30f, -1e30f};
    float l[4] = {};

    const int NT    = SEQ / 64;
    const int ktmax = causal ? qt : (NT - 1);
    const int swz   = tx & 7;

    for (int kt = 0; kt <= ktmax; kt++) {
        __syncthreads();   // prev iter done reading Vs / KP(P); Q load visible on iter 0
        const int k0 = kt * 64;
        #pragma unroll
        for (int t = 0; t < 4; t++) {
            int idx = tid + t * 256;
            int c   = idx >> 4;
            int d4  = idx & 15;
            float4 kv = *(const float4*)(Kg + (size_t)(k0 + c) * THREE_D + d4 * 4);
            int chunk = d4 ^ ((c >> 2) & 7);            // XOR swizzle for conflict-free col reads
            *(float4*)&KP[c * 64 + chunk * 4] = kv;
            float4 vv = *(const float4*)(Vg + (size_t)(k0 + c) * THREE_D + d4 * 4);
            *(float4*)&Vs[c * 64 + d4 * 4] = vv;
        }
        __syncthreads();

        // S = Q @ K^T  (4x4 per thread over dh=64)
        float s[4][4] = {};
        #pragma unroll
        for (int d4 = 0; d4 < 16; d4++) {
            float4 qa[4], kb[4];
            #pragma unroll
            for (int i = 0; i < 4; i++)
                qa[i] = *(const float4*)&Qs[(ty * 4 + i) * 64 + d4 * 4];
            const int ch = (d4 ^ swz) * 4;
            #pragma unroll
            for (int j = 0; j < 4; j++)
                kb[j] = *(const float4*)&KP[(tx * 4 + j) * 64 + ch];
            #pragma unroll
            for (int i = 0; i < 4; i++)
                #pragma unroll
                for (int j = 0; j < 4; j++)
                    s[i][j] += qa[i].x * kb[j].x + qa[i].y * kb[j].y
                             + qa[i].z * kb[j].z + qa[i].w * kb[j].w;
        }

        // online softmax (mask-before-scale == -1e30 either way)
        const bool diag = causal && (kt == qt);
        float corr[4];
        #pragma unroll
        for (int i = 0; i < 4; i++) {
            #pragma unroll
            for (int j = 0; j < 4; j++) {
                float v = s[i][j] * scale;
                if (diag && (tx * 4 + j) > (ty * 4 + i)) v = -1e30f;
                s[i][j] = v;
            }
            float mx = fmaxf(fmaxf(s[i][0], s[i][1]), fmaxf(s[i][2], s[i][3]));
            #pragma unroll
            for (int off = 8; off >= 1; off >>= 1)
                mx = fmaxf(mx, __shfl_xor_sync(0xffffffffu, mx, off, 16));
            float mn = fmaxf(m[i], mx);
            corr[i] = __expf(m[i] - mn);
            m[i] = mn;
            float sum = 0.f;
            #pragma unroll
            for (int j = 0; j < 4; j++) { s[i][j] = __expf(s[i][j] - mn); sum += s[i][j]; }
            #pragma unroll
            for (int off = 8; off >= 1; off >>= 1)
                sum += __shfl_xor_sync(0xffffffffu, sum, off, 16);
            l[i] = l[i] * corr[i] + sum;
            #pragma unroll
            for (int j = 0; j < 4; j++) o[i][j] *= corr[i];
        }

        __syncthreads();   // all warps done reading K from KP — safe to overlay P
        #pragma unroll
        for (int i = 0; i < 4; i++)
            *(float4*)&KP[(ty * 4 + i) * 64 + tx * 4] =
                make_float4(s[i][0], s[i][1], s[i][2], s[i][3]);
        __syncwarp();      // P rows are produced & consumed within one warp

        // O += P @ V
        #pragma unroll
        for (int kk4 = 0; kk4 < 16; kk4++) {
            float4 pa[4];
            #pragma unroll
            for (int i = 0; i < 4; i++)
                pa[i] = *(const float4*)&KP[(ty * 4 + i) * 64 + kk4 * 4];
            #pragma unroll
            for (int kkk = 0; kkk < 4; kkk++) {
                float4 vb = *(const float4*)&Vs[(kk4 * 4 + kkk) * 64 + tx * 4];
                #pragma unroll
                for (int i = 0; i < 4; i++) {
                    float pv = ((const float*)&pa[i])[kkk];
                    o[i][0] += pv * vb.x; o[i][1] += pv * vb.y;
                    o[i][2] += pv * vb.z; o[i][3] += pv * vb.w;
                }
            }
        }
    }

    // normalize + write [B,S,D] layout
    #pragma unroll
    for (int i = 0; i < 4; i++) {
        float inv = 1.0f / l[i];
        int row = b * SEQ + qt * 64 + ty * 4 + i;
        float4 r4 = make_float4(o[i][0] * inv, o[i][1] * inv,
                                o[i][2] * inv, o[i][3] * inv);
        *(float4*)(Out + (size_t)row * DMODEL + h * DH + tx * 4) = r4;
    }
}

// ---------------------------------------------------------------------------
extern "C" void kernel_launch(void* const* d_in, const int* in_sizes, int n_in,
                              void* d_out, int out_size)
{
    (void)in_sizes; (void)n_in; (void)out_size;
    const float* x     = (const float*)d_in[0];
    const float* w_in  = (const float*)d_in[1];
    const float* b_in  = (const float*)d_in[2];
    const float* w_out = (const float*)d_in[3];
    const float* b_out = (const float*)d_in[4];
    const int*   cmask = (const int*)  d_in[5];
    float* out = (float*)d_out;

    float *qkv, *att;
    cudaGetSymbolAddress((void**)&qkv, g_qkv);
    cudaGetSymbolAddress((void**)&att, g_att);

    // 1) qkv = x @ w_in^T + b_in     [4096,1536]
    gemm_nt_bias<<<dim3(THREE_D / 128, MROWS / 128), 256>>>(
        x, w_in, b_in, qkv, MROWS, THREE_D, DMODEL);

    // 2) flash attention -> att [4096,512] in [B,S,D] layout
    flash_attn_kernel<<<dim3(SEQ / 64, BATCH * NHEADS), 256>>>(qkv, cmask, att);

    // 3) out = att @ w_out^T + b_out
    gemm_nt_bias<<<dim3(DMODEL / 128, MROWS / 128), 256>>>(
        att, w_out, b_out, out, MROWS, DMODEL, DMODEL);
}

// round 3
// speedup vs baseline: 1.2802x; 1.2802x over previous
#include <cuda_runtime.h>
#include <cstdint>

// ---------------- problem constants ----------------
#define BATCH   2
#define SEQ     2048
#define DMODEL  512
#define NHEADS  8
#define DH      64
#define MROWS   (BATCH*SEQ)      // 4096
#define THREE_D (3*DMODEL)       // 1536

// scratch (no cudaMalloc allowed)
__device__ float g_qkv[(size_t)MROWS * THREE_D];   // 25.2 MB
__device__ float g_att[(size_t)MROWS * DMODEL];    //  8.4 MB

// ---------------------------------------------------------------------------
// helpers
// ---------------------------------------------------------------------------
__device__ __forceinline__ uint32_t f2tf32(float f) {
    uint32_t r;
    asm("cvt.rna.tf32.f32 %0, %1;" : "=r"(r) : "f"(f));
    return r;
}

__device__ __forceinline__ void mma_tf32(float c[4], uint32_t a0, uint32_t a1,
                                         uint32_t a2, uint32_t a3,
                                         uint32_t b0, uint32_t b1) {
    asm volatile(
        "mma.sync.aligned.m16n8k8.row.col.f32.tf32.tf32.f32 "
        "{%0,%1,%2,%3}, {%4,%5,%6,%7}, {%8,%9}, {%0,%1,%2,%3};"
        : "+f"(c[0]), "+f"(c[1]), "+f"(c[2]), "+f"(c[3])
        : "r"(a0), "r"(a1), "r"(a2), "r"(a3), "r"(b0), "r"(b1));
}

// ===========================================================================
// TF32 mma.sync GEMM: C[M,N] = A[M,K] @ B[N,K]^T + bias[N]
// A, B row-major, K contiguous (NT). CTA tile 128x128, stage K=16.
// 8 warps (4x2): each warp 32 rows x 64 cols = 2 mtiles x 8 ntiles of m16n8k8.
// Smem stride 20 floats => conflict-free fragment LDS (20g+t is perm mod 32).
// ===========================================================================
#define TILE_M  128
#define TILE_N  128
#define STAGE_K 16
#define LDS_STR 20

__global__ __launch_bounds__(256, 2)
void gemm_mma(const float* __restrict__ A, const float* __restrict__ B,
              const float* __restrict__ bias, float* __restrict__ C,
              int M, int N, int K)
{
    __shared__ uint32_t As[TILE_M * LDS_STR];   // 10240 B
    __shared__ uint32_t Bs[TILE_N * LDS_STR];   // 10240 B

    const int tid = threadIdx.x;
    const int wid = tid >> 5;
    const int lane = tid & 31;
    const int g   = lane >> 2;      // groupID 0..7
    const int t   = lane & 3;       // threadID_in_group 0..3
    const int wm  = wid >> 1;       // 0..3
    const int wn  = wid & 1;        // 0..1
    const int bm  = blockIdx.y * TILE_M;
    const int bn  = blockIdx.x * TILE_N;

    const float* Ab = A + (size_t)bm * K;
    const float* Bb = B + (size_t)bn * K;

    // per-thread load slots: idx, idx+256 over 512 chunks (row 0..127, kq 0..3)
    const int row0 = tid >> 2;
    const int kq0  = (tid & 3) << 2;
    const int row1 = (tid + 256) >> 2;
    const int kq1  = ((tid + 256) & 3) << 2;

    float acc[2][8][4] = {};
    float4 pa0, pa1, pb0, pb1;

    // prologue: stage 0
    pa0 = *(const float4*)(Ab + (size_t)row0 * K + kq0);
    pa1 = *(const float4*)(Ab + (size_t)row1 * K + kq1);
    pb0 = *(const float4*)(Bb + (size_t)row0 * K + kq0);
    pb1 = *(const float4*)(Bb + (size_t)row1 * K + kq1);
    {
        uint32_t* d = &As[row0 * LDS_STR + kq0];
        d[0]=f2tf32(pa0.x); d[1]=f2tf32(pa0.y); d[2]=f2tf32(pa0.z); d[3]=f2tf32(pa0.w);
        d = &As[row1 * LDS_STR + kq1];
        d[0]=f2tf32(pa1.x); d[1]=f2tf32(pa1.y); d[2]=f2tf32(pa1.z); d[3]=f2tf32(pa1.w);
        d = &Bs[row0 * LDS_STR + kq0];
        d[0]=f2tf32(pb0.x); d[1]=f2tf32(pb0.y); d[2]=f2tf32(pb0.z); d[3]=f2tf32(pb0.w);
        d = &Bs[row1 * LDS_STR + kq1];
        d[0]=f2tf32(pb1.x); d[1]=f2tf32(pb1.y); d[2]=f2tf32(pb1.z); d[3]=f2tf32(pb1.w);
    }
    __syncthreads();

    const int NS = K / STAGE_K;
    for (int s = 0; s < NS; s++) {
        // prefetch next stage into registers (latency hides behind MMAs)
        if (s + 1 < NS) {
            const int k0 = (s + 1) * STAGE_K;
            pa0 = *(const float4*)(Ab + (size_t)row0 * K + k0 + kq0);
            pa1 = *(const float4*)(Ab + (size_t)row1 * K + k0 + kq1);
            pb0 = *(const float4*)(Bb + (size_t)row0 * K + k0 + kq0);
            pb1 = *(const float4*)(Bb + (size_t)row1 * K + k0 + kq1);
        }

        // compute on current stage
        #pragma unroll
        for (int ks = 0; ks < 2; ks++) {
            const int k0 = ks * 8;
            uint32_t a[2][4];
            #pragma unroll
            for (int mt = 0; mt < 2; mt++) {
                const int m0 = wm * 32 + mt * 16;
                a[mt][0] = As[(m0 + g)     * LDS_STR + k0 + t];
                a[mt][1] = As[(m0 + 8 + g) * LDS_STR + k0 + t];
                a[mt][2] = As[(m0 + g)     * LDS_STR + k0 + t + 4];
                a[mt][3] = As[(m0 + 8 + g) * LDS_STR + k0 + t + 4];
            }
            #pragma unroll
            for (int nt = 0; nt < 8; nt++) {
                const int n0 = wn * 64 + nt * 8;
                uint32_t b0 = Bs[(n0 + g) * LDS_STR + k0 + t];
                uint32_t b1 = Bs[(n0 + g) * LDS_STR + k0 + t + 4];
                mma_tf32(acc[0][nt], a[0][0], a[0][1], a[0][2], a[0][3], b0, b1);
                mma_tf32(acc[1][nt], a[1][0], a[1][1], a[1][2], a[1][3], b0, b1);
            }
        }
        __syncthreads();

        if (s + 1 < NS) {
            uint32_t* d = &As[row0 * LDS_STR + kq0];
            d[0]=f2tf32(pa0.x); d[1]=f2tf32(pa0.y); d[2]=f2tf32(pa0.z); d[3]=f2tf32(pa0.w);
            d = &As[row1 * LDS_STR + kq1];
            d[0]=f2tf32(pa1.x); d[1]=f2tf32(pa1.y); d[2]=f2tf32(pa1.z); d[3]=f2tf32(pa1.w);
            d = &Bs[row0 * LDS_STR + kq0];
            d[0]=f2tf32(pb0.x); d[1]=f2tf32(pb0.y); d[2]=f2tf32(pb0.z); d[3]=f2tf32(pb0.w);
            d = &Bs[row1 * LDS_STR + kq1];
            d[0]=f2tf32(pb1.x); d[1]=f2tf32(pb1.y); d[2]=f2tf32(pb1.z); d[3]=f2tf32(pb1.w);
            __syncthreads();
        }
    }

    // epilogue: C fragment rows m0+g / m0+8+g, cols n0 + t*2 (+1)
    #pragma unroll
    for (int mt = 0; mt < 2; mt++) {
        const int r0 = bm + wm * 32 + mt * 16 + g;
        #pragma unroll
        for (int nt = 0; nt < 8; nt++) {
            const int c0 = bn + wn * 64 + nt * 8 + t * 2;
            float2 bv = *(const float2*)(bias + c0);
            float2 lo = make_float2(acc[mt][nt][0] + bv.x, acc[mt][nt][1] + bv.y);
            float2 hi = make_float2(acc[mt][nt][2] + bv.x, acc[mt][nt][3] + bv.y);
            *(float2*)(C + (size_t)r0 * N + c0)       = lo;
            *(float2*)(C + (size_t)(r0 + 8) * N + c0) = hi;
        }
    }
}

// ---------------------------------------------------------------------------
// Flash attention (fp32, online softmax, causal). UNCHANGED from R1.
// qkv: [4096, 1536] with chunk order q | v | k (reference quirk).
// ---------------------------------------------------------------------------
__global__ __launch_bounds__(256)
void flash_attn_kernel(const float* __restrict__ qkv,
                       const int*   __restrict__ cmask,
                       float* __restrict__ Out)
{
    __shared__ float Qs[64 * 64];
    __shared__ float KP[64 * 64];   // K tile (swizzled), reused for P tile
    __shared__ float Vs[64 * 64];

    const int tid = threadIdx.x;
    const int ty  = tid >> 4;
    const int tx  = tid & 15;
    const int qt  = blockIdx.x;
    const int bh  = blockIdx.y;
    const int b   = bh >> 3;
    const int h   = bh & 7;
    const int causal = cmask[0];
    const float scale = 0.125f;     // 1/sqrt(64)

    const float* base = qkv + (size_t)(b * SEQ) * THREE_D + h * DH;
    const float* Qg = base;               // q chunk (offset 0)
    const float* Vg = base + DMODEL;      // v chunk (offset 512)  <- q,v,k order!
    const float* Kg = base + 2 * DMODEL;  // k chunk (offset 1024)

    {
        const int q0 = qt * 64;
        #pragma unroll
        for (int t = 0; t < 4; t++) {
            int idx = tid + t * 256;
            int r   = idx >> 4;
            int d4  = idx & 15;
            float4 v = *(const float4*)(Qg + (size_t)(q0 + r) * THREE_D + d4 * 4);
            *(float4*)&Qs[r * 64 + d4 * 4] = v;
        }
    }

    float o[4][4] = {};
    float m[4] = {-1e30f, -1e30f, -1e30f, -1e30f};
    float l[4] = {};

    const int NT    = SEQ / 64;
    const int ktmax = causal ? qt : (NT - 1);
    const int swz   = tx & 7;

    for (int kt = 0; kt <= ktmax; kt++) {
        __syncthreads();
        const int k0 = kt * 64;
        #pragma unroll
        for (int t = 0; t < 4; t++) {
            int idx = tid + t * 256;
            int c   = idx >> 4;
            int d4  = idx & 15;
            float4 kv = *(const float4*)(Kg + (size_t)(k0 + c) * THREE_D + d4 * 4);
            int chunk = d4 ^ ((c >> 2) & 7);
            *(float4*)&KP[c * 64 + chunk * 4] = kv;
            float4 vv = *(const float4*)(Vg + (size_t)(k0 + c) * THREE_D + d4 * 4);
            *(float4*)&Vs[c * 64 + d4 * 4] = vv;
        }
        __syncthreads();

        float s[4][4] = {};
        #pragma unroll
        for (int d4 = 0; d4 < 16; d4++) {
            float4 qa[4], kb[4];
            #pragma unroll
            for (int i = 0; i < 4; i++)
                qa[i] = *(const float4*)&Qs[(ty * 4 + i) * 64 + d4 * 4];
            const int ch = (d4 ^ swz) * 4;
            #pragma unroll
            for (int j = 0; j < 4; j++)
                kb[j] = *(const float4*)&KP[(tx * 4 + j) * 64 + ch];
            #pragma unroll
            for (int i = 0; i < 4; i++)
                #pragma unroll
                for (int j = 0; j < 4; j++)
                    s[i][j] += qa[i].x * kb[j].x + qa[i].y * kb[j].y
                             + qa[i].z * kb[j].z + qa[i].w * kb[j].w;
        }

        const bool diag = causal && (kt == qt);
        float corr[4];
        #pragma unroll
        for (int i = 0; i < 4; i++) {
            #pragma unroll
            for (int j = 0; j < 4; j++) {
                float v = s[i][j] * scale;
                if (diag && (tx * 4 + j) > (ty * 4 + i)) v = -1e30f;
                s[i][j] = v;
            }
            float mx = fmaxf(fmaxf(s[i][0], s[i][1]), fmaxf(s[i][2], s[i][3]));
            #pragma unroll
            for (int off = 8; off >= 1; off >>= 1)
                mx = fmaxf(mx, __shfl_xor_sync(0xffffffffu, mx, off, 16));
            float mn = fmaxf(m[i], mx);
            corr[i] = __expf(m[i] - mn);
            m[i] = mn;
            float sum = 0.f;
            #pragma unroll
            for (int j = 0; j < 4; j++) { s[i][j] = __expf(s[i][j] - mn); sum += s[i][j]; }
            #pragma unroll
            for (int off = 8; off >= 1; off >>= 1)
                sum += __shfl_xor_sync(0xffffffffu, sum, off, 16);
            l[i] = l[i] * corr[i] + sum;
            #pragma unroll
            for (int j = 0; j < 4; j++) o[i][j] *= corr[i];
        }

        __syncthreads();
        #pragma unroll
        for (int i = 0; i < 4; i++)
            *(float4*)&KP[(ty * 4 + i) * 64 + tx * 4] =
                make_float4(s[i][0], s[i][1], s[i][2], s[i][3]);
        __syncwarp();

        #pragma unroll
        for (int kk4 = 0; kk4 < 16; kk4++) {
            float4 pa[4];
            #pragma unroll
            for (int i = 0; i < 4; i++)
                pa[i] = *(const float4*)&KP[(ty * 4 + i) * 64 + kk4 * 4];
            #pragma unroll
            for (int kkk = 0; kkk < 4; kkk++) {
                float4 vb = *(const float4*)&Vs[(kk4 * 4 + kkk) * 64 + tx * 4];
                #pragma unroll
                for (int i = 0; i < 4; i++) {
                    float pv = ((const float*)&pa[i])[kkk];
                    o[i][0] += pv * vb.x; o[i][1] += pv * vb.y;
                    o[i][2] += pv * vb.z; o[i][3] += pv * vb.w;
                }
            }
        }
    }

    #pragma unroll
    for (int i = 0; i < 4; i++) {
        float inv = 1.0f / l[i];
        int row = b * SEQ + qt * 64 + ty * 4 + i;
        float4 r4 = make_float4(o[i][0] * inv, o[i][1] * inv,
                                o[i][2] * inv, o[i][3] * inv);
        *(float4*)(Out + (size_t)row * DMODEL + h * DH + tx * 4) = r4;
    }
}

// ---------------------------------------------------------------------------
extern "C" void kernel_launch(void* const* d_in, const int* in_sizes, int n_in,
                              void* d_out, int out_size)
{
    (void)in_sizes; (void)n_in; (void)out_size;
    const float* x     = (const float*)d_in[0];
    const float* w_in  = (const float*)d_in[1];
    const float* b_in  = (const float*)d_in[2];
    const float* w_out = (const float*)d_in[3];
    const float* b_out = (const float*)d_in[4];
    const int*   cmask = (const int*)  d_in[5];
    float* out = (float*)d_out;

    float *qkv, *att;
    cudaGetSymbolAddress((void**)&qkv, g_qkv);
    cudaGetSymbolAddress((void**)&att, g_att);

    // 1) qkv = x @ w_in^T + b_in     [4096,1536]  (mma.sync tf32)
    gemm_mma<<<dim3(THREE_D / TILE_N, MROWS / TILE_M), 256>>>(
        x, w_in, b_in, qkv, MROWS, THREE_D, DMODEL);

    // 2) flash attention -> att [4096,512] in [B,S,D] layout
    flash_attn_kernel<<<dim3(SEQ / 64, BATCH * NHEADS), 256>>>(qkv, cmask, att);

    // 3) out = att @ w_out^T + b_out  (mma.sync tf32)
    gemm_mma<<<dim3(DMODEL / TILE_N, MROWS / TILE_M), 256>>>(
        att, w_out, b_out, out, MROWS, DMODEL, DMODEL);
}

// round 4
// speedup vs baseline: 1.6668x; 1.3019x over previous
#include <cuda_runtime.h>
#include <cstdint>

// ---------------- problem constants ----------------
#define BATCH   2
#define SEQ     2048
#define DMODEL  512
#define NHEADS  8
#define DH      64
#define MROWS   (BATCH*SEQ)      // 4096
#define THREE_D (3*DMODEL)       // 1536

// scratch (no cudaMalloc allowed)
__device__ float g_qkv[(size_t)MROWS * THREE_D];   // 25.2 MB
__device__ float g_att[(size_t)MROWS * DMODEL];    //  8.4 MB

// ---------------------------------------------------------------------------
// helpers
// ---------------------------------------------------------------------------
__device__ __forceinline__ uint32_t f2tf32(float f) {
    uint32_t r;
    asm("cvt.rna.tf32.f32 %0, %1;" : "=r"(r) : "f"(f));
    return r;
}

__device__ __forceinline__ void mma_tf32(float c[4], uint32_t a0, uint32_t a1,
                                         uint32_t a2, uint32_t a3,
                                         uint32_t b0, uint32_t b1) {
    asm volatile(
        "mma.sync.aligned.m16n8k8.row.col.f32.tf32.tf32.f32 "
        "{%0,%1,%2,%3}, {%4,%5,%6,%7}, {%8,%9}, {%0,%1,%2,%3};"
        : "+f"(c[0]), "+f"(c[1]), "+f"(c[2]), "+f"(c[3])
        : "r"(a0), "r"(a1), "r"(a2), "r"(a3), "r"(b0), "r"(b1));
}

// split a float into tf32 hi + tf32 lo (residual)
__device__ __forceinline__ void store_split4(uint32_t* hi, uint32_t* lo, float4 v) {
    uint32_t h;
    h = f2tf32(v.x); hi[0] = h; lo[0] = f2tf32(v.x - __uint_as_float(h));
    h = f2tf32(v.y); hi[1] = h; lo[1] = f2tf32(v.y - __uint_as_float(h));
    h = f2tf32(v.z); hi[2] = h; lo[2] = f2tf32(v.z - __uint_as_float(h));
    h = f2tf32(v.w); hi[3] = h; lo[3] = f2tf32(v.w - __uint_as_float(h));
}

// ===========================================================================
// Split-TF32 (3-pass) mma.sync GEMM: C = A @ B^T + bias, near-fp32 accuracy.
// A, B row-major NT. CTA tile 128x128, stage K=16, 8 warps (4x2).
// ===========================================================================
#define TILE_M  128
#define TILE_N  128
#define STAGE_K 16
#define LDS_STR 20

__global__ __launch_bounds__(256, 2)
void gemm_mma(const float* __restrict__ A, const float* __restrict__ B,
              const float* __restrict__ bias, float* __restrict__ C,
              int M, int N, int K)
{
    __shared__ uint32_t AsH[TILE_M * LDS_STR];
    __shared__ uint32_t AsL[TILE_M * LDS_STR];
    __shared__ uint32_t BsH[TILE_N * LDS_STR];
    __shared__ uint32_t BsL[TILE_N * LDS_STR];

    const int tid = threadIdx.x;
    const int wid = tid >> 5;
    const int lane = tid & 31;
    const int g   = lane >> 2;
    const int t   = lane & 3;
    const int wm  = wid >> 1;
    const int wn  = wid & 1;
    const int bm  = blockIdx.y * TILE_M;
    const int bn  = blockIdx.x * TILE_N;

    const float* Ab = A + (size_t)bm * K;
    const float* Bb = B + (size_t)bn * K;

    const int row0 = tid >> 2;
    const int kq0  = (tid & 3) << 2;
    const int row1 = (tid + 256) >> 2;
    const int kq1  = ((tid + 256) & 3) << 2;

    float acc[2][8][4] = {};
    float4 pa0, pa1, pb0, pb1;

    pa0 = *(const float4*)(Ab + (size_t)row0 * K + kq0);
    pa1 = *(const float4*)(Ab + (size_t)row1 * K + kq1);
    pb0 = *(const float4*)(Bb + (size_t)row0 * K + kq0);
    pb1 = *(const float4*)(Bb + (size_t)row1 * K + kq1);
    store_split4(&AsH[row0*LDS_STR+kq0], &AsL[row0*LDS_STR+kq0], pa0);
    store_split4(&AsH[row1*LDS_STR+kq1], &AsL[row1*LDS_STR+kq1], pa1);
    store_split4(&BsH[row0*LDS_STR+kq0], &BsL[row0*LDS_STR+kq0], pb0);
    store_split4(&BsH[row1*LDS_STR+kq1], &BsL[row1*LDS_STR+kq1], pb1);
    __syncthreads();

    const int NS = K / STAGE_K;
    for (int s = 0; s < NS; s++) {
        if (s + 1 < NS) {
            const int k0 = (s + 1) * STAGE_K;
            pa0 = *(const float4*)(Ab + (size_t)row0 * K + k0 + kq0);
            pa1 = *(const float4*)(Ab + (size_t)row1 * K + k0 + kq1);
            pb0 = *(const float4*)(Bb + (size_t)row0 * K + k0 + kq0);
            pb1 = *(const float4*)(Bb + (size_t)row1 * K + k0 + kq1);
        }

        #pragma unroll
        for (int ks = 0; ks < 2; ks++) {
            const int k0 = ks * 8;
            uint32_t ah[2][4], al[2][4];
            #pragma unroll
            for (int mt = 0; mt < 2; mt++) {
                const int m0 = wm * 32 + mt * 16;
                ah[mt][0] = AsH[(m0 + g)     * LDS_STR + k0 + t];
                ah[mt][1] = AsH[(m0 + 8 + g) * LDS_STR + k0 + t];
                ah[mt][2] = AsH[(m0 + g)     * LDS_STR + k0 + t + 4];
                ah[mt][3] = AsH[(m0 + 8 + g) * LDS_STR + k0 + t + 4];
                al[mt][0] = AsL[(m0 + g)     * LDS_STR + k0 + t];
                al[mt][1] = AsL[(m0 + 8 + g) * LDS_STR + k0 + t];
                al[mt][2] = AsL[(m0 + g)     * LDS_STR + k0 + t + 4];
                al[mt][3] = AsL[(m0 + 8 + g) * LDS_STR + k0 + t + 4];
            }
            #pragma unroll
            for (int nt = 0; nt < 8; nt++) {
                const int n0 = wn * 64 + nt * 8;
                uint32_t bh0 = BsH[(n0 + g) * LDS_STR + k0 + t];
                uint32_t bh1 = BsH[(n0 + g) * LDS_STR + k0 + t + 4];
                uint32_t bl0 = BsL[(n0 + g) * LDS_STR + k0 + t];
                uint32_t bl1 = BsL[(n0 + g) * LDS_STR + k0 + t + 4];
                #pragma unroll
                for (int mt = 0; mt < 2; mt++) {
                    mma_tf32(acc[mt][nt], ah[mt][0], ah[mt][1], ah[mt][2], ah[mt][3], bh0, bh1);
                    mma_tf32(acc[mt][nt], al[mt][0], al[mt][1], al[mt][2], al[mt][3], bh0, bh1);
                    mma_tf32(acc[mt][nt], ah[mt][0], ah[mt][1], ah[mt][2], ah[mt][3], bl0, bl1);
                }
            }
        }
        __syncthreads();

        if (s + 1 < NS) {
            store_split4(&AsH[row0*LDS_STR+kq0], &AsL[row0*LDS_STR+kq0], pa0);
            store_split4(&AsH[row1*LDS_STR+kq1], &AsL[row1*LDS_STR+kq1], pa1);
            store_split4(&BsH[row0*LDS_STR+kq0], &BsL[row0*LDS_STR+kq0], pb0);
            store_split4(&BsH[row1*LDS_STR+kq1], &BsL[row1*LDS_STR+kq1], pb1);
            __syncthreads();
        }
    }

    #pragma unroll
    for (int mt = 0; mt < 2; mt++) {
        const int r0 = bm + wm * 32 + mt * 16 + g;
        #pragma unroll
        for (int nt = 0; nt < 8; nt++) {
            const int c0 = bn + wn * 64 + nt * 8 + t * 2;
            float2 bv = *(const float2*)(bias + c0);
            float2 lo = make_float2(acc[mt][nt][0] + bv.x, acc[mt][nt][1] + bv.y);
            float2 hi = make_float2(acc[mt][nt][2] + bv.x, acc[mt][nt][3] + bv.y);
            *(float2*)(C + (size_t)r0 * N + c0)       = lo;
            *(float2*)(C + (size_t)(r0 + 8) * N + c0) = hi;
        }
    }
}

// ===========================================================================
// Flash attention on tensor pipe (single-pass tf32).
// qkv: [4096,1536] chunk order q|v|k. Q tile 128 rows, K tile 128 keys.
// 8 warps, warp w owns q rows [16w,16w+16). Smem (dynamic, 104448B):
//   Qs[128][68] tf32 (pre-scaled), Ks[128][68] tf32, Vlin[128][68] tf32.
// P stays in regs; C-frag -> A-frag via shuffles. Vlin read gives free V^T.
// ===========================================================================
#define ATT_STR  68
#define ATT_SMEM (3 * 128 * ATT_STR * 4)   // 104448

__global__ __launch_bounds__(256)
void flash_attn_tc(const float* __restrict__ qkv,
                   const int*   __restrict__ cmask,
                   float* __restrict__ Out)
{
    extern __shared__ uint32_t sm[];
    uint32_t* Qs   = sm;
    uint32_t* Ks   = sm + 128 * ATT_STR;
    uint32_t* Vlin = sm + 2 * 128 * ATT_STR;

    const int tid  = threadIdx.x;
    const int wid  = tid >> 5;
    const int lane = tid & 31;
    const int g    = lane >> 2;
    const int t    = lane & 3;
    const int qt   = (SEQ / 128 - 1) - blockIdx.x;   // descending: LPT schedule
    const int bh   = blockIdx.y;
    const int b    = bh >> 3;
    const int h    = bh & 7;
    const int causal = cmask[0];

    const float* base = qkv + (size_t)(b * SEQ) * THREE_D + h * DH;
    const float* Qg = base;               // q chunk
    const float* Vg = base + DMODEL;      // v chunk (q|v|k quirk)
    const float* Kg = base + 2 * DMODEL;  // k chunk

    const int q0 = qt * 128;

    // load Q tile, fold softmax scale (1/8, exact)
    #pragma unroll
    for (int tt = 0; tt < 8; tt++) {
        int idx = tid + tt * 256;
        int r   = idx >> 4;
        int c4  = (idx & 15) * 4;
        float4 v = *(const float4*)(Qg + (size_t)(q0 + r) * THREE_D + c4);
        uint32_t* d = &Qs[r * ATT_STR + c4];
        d[0] = f2tf32(v.x * 0.125f); d[1] = f2tf32(v.y * 0.125f);
        d[2] = f2tf32(v.z * 0.125f); d[3] = f2tf32(v.w * 0.125f);
    }

    float o[8][4] = {};
    float mA = -1e30f, mB = -1e30f, lA = 0.f, lB = 0.f;
    const int m0   = wid * 16;
    const int rowA = q0 + m0 + g;
    const int rowB = rowA + 8;
    const int src1 = g * 4 + (t >> 1);
    const int src2 = src1 + 2;
    const int sel  = t & 1;

    const int NKT = causal ? (qt + 1) : (SEQ / 128);
    for (int kt = 0; kt < NKT; kt++) {
        __syncthreads();   // prev iter done reading Ks/Vlin (Qs load visible iter 0)
        const int k0 = kt * 128;
        #pragma unroll
        for (int tt = 0; tt < 8; tt++) {
            int idx = tid + tt * 256;
            int r   = idx >> 4;
            int c4  = (idx & 15) * 4;
            float4 kv = *(const float4*)(Kg + (size_t)(k0 + r) * THREE_D + c4);
            uint32_t* dk = &Ks[r * ATT_STR + c4];
            dk[0] = f2tf32(kv.x); dk[1] = f2tf32(kv.y);
            dk[2] = f2tf32(kv.z); dk[3] = f2tf32(kv.w);
            float4 vv = *(const float4*)(Vg + (size_t)(k0 + r) * THREE_D + c4);
            uint32_t* dv = &Vlin[r * ATT_STR + c4];
            dv[0] = f2tf32(vv.x); dv[1] = f2tf32(vv.y);
            dv[2] = f2tf32(vv.z); dv[3] = f2tf32(vv.w);
        }
        __syncthreads();

        // S = (Q*scale) @ K^T : 16 rows x 128 cols per warp
        float s[16][4];
        #pragma unroll
        for (int nt = 0; nt < 16; nt++)
            s[nt][0] = s[nt][1] = s[nt][2] = s[nt][3] = 0.f;
        #pragma unroll
        for (int ks = 0; ks < 8; ks++) {
            const int k8 = ks * 8;
            uint32_t a0 = Qs[(m0 + g)     * ATT_STR + k8 + t];
            uint32_t a1 = Qs[(m0 + 8 + g) * ATT_STR + k8 + t];
            uint32_t a2 = Qs[(m0 + g)     * ATT_STR + k8 + t + 4];
            uint32_t a3 = Qs[(m0 + 8 + g) * ATT_STR + k8 + t + 4];
            #pragma unroll
            for (int nt = 0; nt < 16; nt++) {
                uint32_t b0 = Ks[(nt * 8 + g) * ATT_STR + k8 + t];
                uint32_t b1 = Ks[(nt * 8 + g) * ATT_STR + k8 + t + 4];
                mma_tf32(s[nt], a0, a1, a2, a3, b0, b1);
            }
        }

        // causal mask (only the diagonal tile needs it)
        if (causal && kt == qt) {
            #pragma unroll
            for (int nt = 0; nt < 16; nt++) {
                const int c = k0 + nt * 8 + 2 * t;
                if (c     > rowA) s[nt][0] = -1e30f;
                if (c + 1 > rowA) s[nt][1] = -1e30f;
                if (c     > rowB) s[nt][2] = -1e30f;
                if (c + 1 > rowB) s[nt][3] = -1e30f;
            }
        }

        // online softmax (rows rA, rB per thread; reduce over t-quad)
        float mxA = -1e30f, mxB = -1e30f;
        #pragma unroll
        for (int nt = 0; nt < 16; nt++) {
            mxA = fmaxf(mxA, fmaxf(s[nt][0], s[nt][1]));
            mxB = fmaxf(mxB, fmaxf(s[nt][2], s[nt][3]));
        }
        mxA = fmaxf(mxA, __shfl_xor_sync(0xffffffffu, mxA, 1));
        mxA = fmaxf(mxA, __shfl_xor_sync(0xffffffffu, mxA, 2));
        mxB = fmaxf(mxB, __shfl_xor_sync(0xffffffffu, mxB, 1));
        mxB = fmaxf(mxB, __shfl_xor_sync(0xffffffffu, mxB, 2));
        const float mnA = fmaxf(mA, mxA);
        const float mnB = fmaxf(mB, mxB);
        const float corrA = __expf(mA - mnA);
        const float corrB = __expf(mB - mnB);
        mA = mnA; mB = mnB;

        float sumA = 0.f, sumB = 0.f;
        #pragma unroll
        for (int nt = 0; nt < 16; nt++) {
            float p0 = __expf(s[nt][0] - mnA);
            float p1 = __expf(s[nt][1] - mnA);
            float p2 = __expf(s[nt][2] - mnB);
            float p3 = __expf(s[nt][3] - mnB);
            sumA += p0 + p1;
            sumB += p2 + p3;
            s[nt][0] = __uint_as_float(f2tf32(p0));
            s[nt][1] = __uint_as_float(f2tf32(p1));
            s[nt][2] = __uint_as_float(f2tf32(p2));
            s[nt][3] = __uint_as_float(f2tf32(p3));
        }
        sumA += __shfl_xor_sync(0xffffffffu, sumA, 1);
        sumA += __shfl_xor_sync(0xffffffffu, sumA, 2);
        sumB += __shfl_xor_sync(0xffffffffu, sumB, 1);
        sumB += __shfl_xor_sync(0xffffffffu, sumB, 2);
        lA = lA * corrA + sumA;
        lB = lB * corrB + sumB;
        #pragma unroll
        for (int nt = 0; nt < 8; nt++) {
            o[nt][0] *= corrA; o[nt][1] *= corrA;
            o[nt][2] *= corrB; o[nt][3] *= corrB;
        }

        // O += P @ V ; A-frag from P C-frags via shuffle, B from Vlin (free ^T)
        #pragma unroll
        for (int ks = 0; ks < 16; ks++) {
            uint32_t x0, x1;
            x0 = __shfl_sync(0xffffffffu, __float_as_uint(s[ks][0]), src1);
            x1 = __shfl_sync(0xffffffffu, __float_as_uint(s[ks][1]), src1);
            uint32_t a0 = sel ? x1 : x0;
            x0 = __shfl_sync(0xffffffffu, __float_as_uint(s[ks][2]), src1);
            x1 = __shfl_sync(0xffffffffu, __float_as_uint(s[ks][3]), src1);
            uint32_t a1 = sel ? x1 : x0;
            x0 = __shfl_sync(0xffffffffu, __float_as_uint(s[ks][0]), src2);
            x1 = __shfl_sync(0xffffffffu, __float_as_uint(s[ks][1]), src2);
            uint32_t a2 = sel ? x1 : x0;
            x0 = __shfl_sync(0xffffffffu, __float_as_uint(s[ks][2]), src2);
            x1 = __shfl_sync(0xffffffffu, __float_as_uint(s[ks][3]), src2);
            uint32_t a3 = sel ? x1 : x0;
            #pragma unroll
            for (int nt = 0; nt < 8; nt++) {
                uint32_t b0 = Vlin[(ks * 8 + t)     * ATT_STR + nt * 8 + g];
                uint32_t b1 = Vlin[(ks * 8 + t + 4) * ATT_STR + nt * 8 + g];
                mma_tf32(o[nt], a0, a1, a2, a3, b0, b1);
            }
        }
    }

    // epilogue: normalize, write [B,S,D]
    const float invA = 1.0f / lA;
    const float invB = 1.0f / lB;
    float* OrA = Out + (size_t)(b * SEQ + rowA) * DMODEL + h * DH;
    float* OrB = Out + (size_t)(b * SEQ + rowB) * DMODEL + h * DH;
    #pragma unroll
    for (int nt = 0; nt < 8; nt++) {
        const int c = nt * 8 + 2 * t;
        *(float2*)(OrA + c) = make_float2(o[nt][0] * invA, o[nt][1] * invA);
        *(float2*)(OrB + c) = make_float2(o[nt][2] * invB, o[nt][3] * invB);
    }
}

// ---------------------------------------------------------------------------
extern "C" void kernel_launch(void* const* d_in, const int* in_sizes, int n_in,
                              void* d_out, int out_size)
{
    (void)in_sizes; (void)n_in; (void)out_size;
    const float* x     = (const float*)d_in[0];
    const float* w_in  = (const float*)d_in[1];
    const float* b_in  = (const float*)d_in[2];
    const float* w_out = (const float*)d_in[3];
    const float* b_out = (const float*)d_in[4];
    const int*   cmask = (const int*)  d_in[5];
    float* out = (float*)d_out;

    float *qkv, *att;
    cudaGetSymbolAddress((void**)&qkv, g_qkv);
    cudaGetSymbolAddress((void**)&att, g_att);

    // idempotent, legal during capture (not a stream op)
    cudaFuncSetAttribute(flash_attn_tc,
                         cudaFuncAttributeMaxDynamicSharedMemorySize, ATT_SMEM);

    // 1) qkv = x @ w_in^T + b_in   (split-tf32, near-fp32)
    gemm_mma<<<dim3(THREE_D / TILE_N, MROWS / TILE_M), 256>>>(
        x, w_in, b_in, qkv, MROWS, THREE_D, DMODEL);

    // 2) flash attention on tensor pipe -> att [B,S,D]
    flash_attn_tc<<<dim3(SEQ / 128, BATCH * NHEADS), 256, ATT_SMEM>>>(
        qkv, cmask, att);

    // 3) out = att @ w_out^T + b_out  (split-tf32)
    gemm_mma<<<dim3(DMODEL / TILE_N, MROWS / TILE_M), 256>>>(
        att, w_out, b_out, out, MROWS, DMODEL, DMODEL);
}

// round 5
// speedup vs baseline: 2.0894x; 1.2536x over previous
#include <cuda_runtime.h>
#include <cstdint>

// ---------------- problem constants ----------------
#define BATCH   2
#define SEQ     2048
#define DMODEL  512
#define NHEADS  8
#define DH      64
#define MROWS   (BATCH*SEQ)      // 4096
#define THREE_D (3*DMODEL)       // 1536

// scratch (no cudaMalloc allowed)
__device__ float g_qkv[(size_t)MROWS * THREE_D];   // 25.2 MB
__device__ float g_att[(size_t)MROWS * DMODEL];    //  8.4 MB

// ---------------------------------------------------------------------------
// helpers
// ---------------------------------------------------------------------------
__device__ __forceinline__ uint32_t f2tf32(float f) {
    uint32_t r;
    asm("cvt.rna.tf32.f32 %0, %1;" : "=r"(r) : "f"(f));
    return r;
}

__device__ __forceinline__ void mma_tf32(float c[4], uint32_t a0, uint32_t a1,
                                         uint32_t a2, uint32_t a3,
                                         uint32_t b0, uint32_t b1) {
    asm volatile(
        "mma.sync.aligned.m16n8k8.row.col.f32.tf32.tf32.f32 "
        "{%0,%1,%2,%3}, {%4,%5,%6,%7}, {%8,%9}, {%0,%1,%2,%3};"
        : "+f"(c[0]), "+f"(c[1]), "+f"(c[2]), "+f"(c[3])
        : "r"(a0), "r"(a1), "r"(a2), "r"(a3), "r"(b0), "r"(b1));
}

// ===========================================================================
// Single-pass TF32 mma.sync GEMM: C = A @ B^T + bias (validated R3 version).
// A, B row-major NT. CTA tile 128x128, stage K=16, 8 warps (4x2).
// ===========================================================================
#define TILE_M  128
#define TILE_N  128
#define STAGE_K 16
#define LDS_STR 20

__global__ __launch_bounds__(256, 2)
void gemm_mma(const float* __restrict__ A, const float* __restrict__ B,
              const float* __restrict__ bias, float* __restrict__ C,
              int M, int N, int K)
{
    __shared__ uint32_t As[TILE_M * LDS_STR];
    __shared__ uint32_t Bs[TILE_N * LDS_STR];

    const int tid = threadIdx.x;
    const int wid = tid >> 5;
    const int lane = tid & 31;
    const int g   = lane >> 2;
    const int t   = lane & 3;
    const int wm  = wid >> 1;
    const int wn  = wid & 1;
    const int bm  = blockIdx.y * TILE_M;
    const int bn  = blockIdx.x * TILE_N;

    const float* Ab = A + (size_t)bm * K;
    const float* Bb = B + (size_t)bn * K;

    const int row0 = tid >> 2;
    const int kq0  = (tid & 3) << 2;
    const int row1 = (tid + 256) >> 2;
    const int kq1  = ((tid + 256) & 3) << 2;

    float acc[2][8][4] = {};
    float4 pa0, pa1, pb0, pb1;

    pa0 = *(const float4*)(Ab + (size_t)row0 * K + kq0);
    pa1 = *(const float4*)(Ab + (size_t)row1 * K + kq1);
    pb0 = *(const float4*)(Bb + (size_t)row0 * K + kq0);
    pb1 = *(const float4*)(Bb + (size_t)row1 * K + kq1);
    {
        uint32_t* d = &As[row0 * LDS_STR + kq0];
        d[0]=f2tf32(pa0.x); d[1]=f2tf32(pa0.y); d[2]=f2tf32(pa0.z); d[3]=f2tf32(pa0.w);
        d = &As[row1 * LDS_STR + kq1];
        d[0]=f2tf32(pa1.x); d[1]=f2tf32(pa1.y); d[2]=f2tf32(pa1.z); d[3]=f2tf32(pa1.w);
        d = &Bs[row0 * LDS_STR + kq0];
        d[0]=f2tf32(pb0.x); d[1]=f2tf32(pb0.y); d[2]=f2tf32(pb0.z); d[3]=f2tf32(pb0.w);
        d = &Bs[row1 * LDS_STR + kq1];
        d[0]=f2tf32(pb1.x); d[1]=f2tf32(pb1.y); d[2]=f2tf32(pb1.z); d[3]=f2tf32(pb1.w);
    }
    __syncthreads();

    const int NS = K / STAGE_K;
    for (int s = 0; s < NS; s++) {
        if (s + 1 < NS) {
            const int k0 = (s + 1) * STAGE_K;
            pa0 = *(const float4*)(Ab + (size_t)row0 * K + k0 + kq0);
            pa1 = *(const float4*)(Ab + (size_t)row1 * K + k0 + kq1);
            pb0 = *(const float4*)(Bb + (size_t)row0 * K + k0 + kq0);
            pb1 = *(const float4*)(Bb + (size_t)row1 * K + k0 + kq1);
        }

        #pragma unroll
        for (int ks = 0; ks < 2; ks++) {
            const int k0 = ks * 8;
            uint32_t a[2][4];
            #pragma unroll
            for (int mt = 0; mt < 2; mt++) {
                const int m0 = wm * 32 + mt * 16;
                a[mt][0] = As[(m0 + g)     * LDS_STR + k0 + t];
                a[mt][1] = As[(m0 + 8 + g) * LDS_STR + k0 + t];
                a[mt][2] = As[(m0 + g)     * LDS_STR + k0 + t + 4];
                a[mt][3] = As[(m0 + 8 + g) * LDS_STR + k0 + t + 4];
            }
            #pragma unroll
            for (int nt = 0; nt < 8; nt++) {
                const int n0 = wn * 64 + nt * 8;
                uint32_t b0 = Bs[(n0 + g) * LDS_STR + k0 + t];
                uint32_t b1 = Bs[(n0 + g) * LDS_STR + k0 + t + 4];
                mma_tf32(acc[0][nt], a[0][0], a[0][1], a[0][2], a[0][3], b0, b1);
                mma_tf32(acc[1][nt], a[1][0], a[1][1], a[1][2], a[1][3], b0, b1);
            }
        }
        __syncthreads();

        if (s + 1 < NS) {
            uint32_t* d = &As[row0 * LDS_STR + kq0];
            d[0]=f2tf32(pa0.x); d[1]=f2tf32(pa0.y); d[2]=f2tf32(pa0.z); d[3]=f2tf32(pa0.w);
            d = &As[row1 * LDS_STR + kq1];
            d[0]=f2tf32(pa1.x); d[1]=f2tf32(pa1.y); d[2]=f2tf32(pa1.z); d[3]=f2tf32(pa1.w);
            d = &Bs[row0 * LDS_STR + kq0];
            d[0]=f2tf32(pb0.x); d[1]=f2tf32(pb0.y); d[2]=f2tf32(pb0.z); d[3]=f2tf32(pb0.w);
            d = &Bs[row1 * LDS_STR + kq1];
            d[0]=f2tf32(pb1.x); d[1]=f2tf32(pb1.y); d[2]=f2tf32(pb1.z); d[3]=f2tf32(pb1.w);
            __syncthreads();
        }
    }

    #pragma unroll
    for (int mt = 0; mt < 2; mt++) {
        const int r0 = bm + wm * 32 + mt * 16 + g;
        #pragma unroll
        for (int nt = 0; nt < 8; nt++) {
            const int c0 = bn + wn * 64 + nt * 8 + t * 2;
            float2 bv = *(const float2*)(bias + c0);
            float2 lo = make_float2(acc[mt][nt][0] + bv.x, acc[mt][nt][1] + bv.y);
            float2 hi = make_float2(acc[mt][nt][2] + bv.x, acc[mt][nt][3] + bv.y);
            *(float2*)(C + (size_t)r0 * N + c0)       = lo;
            *(float2*)(C + (size_t)(r0 + 8) * N + c0) = hi;
        }
    }
}

// ===========================================================================
// Flash attention on tensor pipe (tf32) with double-buffered K/V tiles.
// qkv: [4096,1536] chunk order q|v|k. Q tile 128 rows, K tile 128 keys.
// 8 warps, warp w owns q rows [16w,16w+16).
// Smem (dynamic, 174080B): Qs + 2x Ks + 2x Vs, each [128][68] tf32.
// One barrier per kt: next-tile LDGs issued before QK, STS after softmax
// (top-of-loop barrier guarantees iter kt-1 compute is done in all warps).
// ===========================================================================
#define ATT_STR  68
#define ATT_TILE (128 * ATT_STR)
#define ATT_SMEM (5 * ATT_TILE * 4)   // 174080

__global__ __launch_bounds__(256)
void flash_attn_tc(const float* __restrict__ qkv,
                   const int*   __restrict__ cmask,
                   float* __restrict__ Out)
{
    extern __shared__ uint32_t sm[];
    uint32_t* Qs = sm;
    uint32_t* KsB[2] = { sm + ATT_TILE,     sm + 2 * ATT_TILE };
    uint32_t* VsB[2] = { sm + 3 * ATT_TILE, sm + 4 * ATT_TILE };

    const int tid  = threadIdx.x;
    const int wid  = tid >> 5;
    const int lane = tid & 31;
    const int g    = lane >> 2;
    const int t    = lane & 3;
    const int qt   = (SEQ / 128 - 1) - blockIdx.x;   // descending: LPT schedule
    const int bh   = blockIdx.y;
    const int b    = bh >> 3;
    const int h    = bh & 7;
    const int causal = cmask[0];

    const float* base = qkv + (size_t)(b * SEQ) * THREE_D + h * DH;
    const float* Qg = base;               // q chunk
    const float* Vg = base + DMODEL;      // v chunk (q|v|k quirk)
    const float* Kg = base + 2 * DMODEL;  // k chunk

    const int q0 = qt * 128;
    const int lr  = tid >> 4;            // per-thread load row 0..15 step via tt
    const int lc4 = (tid & 15) * 4;      // load col (x4)

    // load Q tile (scale folded, exact) + prologue K/V tile 0 into buf 0
    #pragma unroll
    for (int tt = 0; tt < 8; tt++) {
        const int r = lr + tt * 16;
        float4 v = *(const float4*)(Qg + (size_t)(q0 + r) * THREE_D + lc4);
        uint32_t* d = &Qs[r * ATT_STR + lc4];
        d[0] = f2tf32(v.x * 0.125f); d[1] = f2tf32(v.y * 0.125f);
        d[2] = f2tf32(v.z * 0.125f); d[3] = f2tf32(v.w * 0.125f);
        float4 kv = *(const float4*)(Kg + (size_t)r * THREE_D + lc4);
        uint32_t* dk = &KsB[0][r * ATT_STR + lc4];
        dk[0] = f2tf32(kv.x); dk[1] = f2tf32(kv.y);
        dk[2] = f2tf32(kv.z); dk[3] = f2tf32(kv.w);
        float4 vv = *(const float4*)(Vg + (size_t)r * THREE_D + lc4);
        uint32_t* dv = &VsB[0][r * ATT_STR + lc4];
        dv[0] = f2tf32(vv.x); dv[1] = f2tf32(vv.y);
        dv[2] = f2tf32(vv.z); dv[3] = f2tf32(vv.w);
    }

    float o[8][4] = {};
    float mA = -1e30f, mB = -1e30f, lA = 0.f, lB = 0.f;
    const int m0   = wid * 16;
    const int rowA = q0 + m0 + g;
    const int rowB = rowA + 8;
    const int src1 = g * 4 + (t >> 1);
    const int src2 = src1 + 2;
    const int sel  = t & 1;

    const int NKT = causal ? (qt + 1) : (SEQ / 128);
    for (int kt = 0; kt < NKT; kt++) {
        __syncthreads();   // buf[kt&1] fully stored; all warps done with iter kt-1
        const uint32_t* Kcur = KsB[kt & 1];
        const uint32_t* Vcur = VsB[kt & 1];
        const bool pre = (kt + 1 < NKT);

        // issue next-tile loads early (latency hides behind QK + softmax)
        float4 pk[8], pv[8];
        if (pre) {
            const int kn = (kt + 1) * 128;
            #pragma unroll
            for (int tt = 0; tt < 8; tt++) {
                const int r = kn + lr + tt * 16;
                pk[tt] = *(const float4*)(Kg + (size_t)r * THREE_D + lc4);
                pv[tt] = *(const float4*)(Vg + (size_t)r * THREE_D + lc4);
            }
        }

        // S = (Q*scale) @ K^T : 16 rows x 128 cols per warp
        float s[16][4];
        #pragma unroll
        for (int nt = 0; nt < 16; nt++)
            s[nt][0] = s[nt][1] = s[nt][2] = s[nt][3] = 0.f;
        #pragma unroll
        for (int ks = 0; ks < 8; ks++) {
            const int k8 = ks * 8;
            uint32_t a0 = Qs[(m0 + g)     * ATT_STR + k8 + t];
            uint32_t a1 = Qs[(m0 + 8 + g) * ATT_STR + k8 + t];
            uint32_t a2 = Qs[(m0 + g)     * ATT_STR + k8 + t + 4];
            uint32_t a3 = Qs[(m0 + 8 + g) * ATT_STR + k8 + t + 4];
            #pragma unroll
            for (int nt = 0; nt < 16; nt++) {
                uint32_t b0 = Kcur[(nt * 8 + g) * ATT_STR + k8 + t];
                uint32_t b1 = Kcur[(nt * 8 + g) * ATT_STR + k8 + t + 4];
                mma_tf32(s[nt], a0, a1, a2, a3, b0, b1);
            }
        }

        // causal mask (diagonal tile only)
        if (causal && kt == qt) {
            const int k0 = kt * 128;
            #pragma unroll
            for (int nt = 0; nt < 16; nt++) {
                const int c = k0 + nt * 8 + 2 * t;
                if (c     > rowA) s[nt][0] = -1e30f;
                if (c + 1 > rowA) s[nt][1] = -1e30f;
                if (c     > rowB) s[nt][2] = -1e30f;
                if (c + 1 > rowB) s[nt][3] = -1e30f;
            }
        }

        // online softmax (rows rA, rB; reduce over t-quad)
        float mxA = -1e30f, mxB = -1e30f;
        #pragma unroll
        for (int nt = 0; nt < 16; nt++) {
            mxA = fmaxf(mxA, fmaxf(s[nt][0], s[nt][1]));
            mxB = fmaxf(mxB, fmaxf(s[nt][2], s[nt][3]));
        }
        mxA = fmaxf(mxA, __shfl_xor_sync(0xffffffffu, mxA, 1));
        mxA = fmaxf(mxA, __shfl_xor_sync(0xffffffffu, mxA, 2));
        mxB = fmaxf(mxB, __shfl_xor_sync(0xffffffffu, mxB, 1));
        mxB = fmaxf(mxB, __shfl_xor_sync(0xffffffffu, mxB, 2));
        const float mnA = fmaxf(mA, mxA);
        const float mnB = fmaxf(mB, mxB);
        const float corrA = __expf(mA - mnA);
        const float corrB = __expf(mB - mnB);
        mA = mnA; mB = mnB;

        float sumA = 0.f, sumB = 0.f;
        #pragma unroll
        for (int nt = 0; nt < 16; nt++) {
            float p0 = __expf(s[nt][0] - mnA);
            float p1 = __expf(s[nt][1] - mnA);
            float p2 = __expf(s[nt][2] - mnB);
            float p3 = __expf(s[nt][3] - mnB);
            sumA += p0 + p1;
            sumB += p2 + p3;
            s[nt][0] = __uint_as_float(f2tf32(p0));
            s[nt][1] = __uint_as_float(f2tf32(p1));
            s[nt][2] = __uint_as_float(f2tf32(p2));
            s[nt][3] = __uint_as_float(f2tf32(p3));
        }
        sumA += __shfl_xor_sync(0xffffffffu, sumA, 1);
        sumA += __shfl_xor_sync(0xffffffffu, sumA, 2);
        sumB += __shfl_xor_sync(0xffffffffu, sumB, 1);
        sumB += __shfl_xor_sync(0xffffffffu, sumB, 2);
        lA = lA * corrA + sumA;
        lB = lB * corrB + sumB;
        #pragma unroll
        for (int nt = 0; nt < 8; nt++) {
            o[nt][0] *= corrA; o[nt][1] *= corrA;
            o[nt][2] *= corrB; o[nt][3] *= corrB;
        }

        // store next tile into the other buffer (safe: top barrier passed,
        // its previous readers — iter kt-1 compute — are all done)
        if (pre) {
            uint32_t* Knxt = KsB[(kt + 1) & 1];
            uint32_t* Vnxt = VsB[(kt + 1) & 1];
            #pragma unroll
            for (int tt = 0; tt < 8; tt++) {
                const int r = lr + tt * 16;
                uint32_t* dk = &Knxt[r * ATT_STR + lc4];
                dk[0] = f2tf32(pk[tt].x); dk[1] = f2tf32(pk[tt].y);
                dk[2] = f2tf32(pk[tt].z); dk[3] = f2tf32(pk[tt].w);
                uint32_t* dv = &Vnxt[r * ATT_STR + lc4];
                dv[0] = f2tf32(pv[tt].x); dv[1] = f2tf32(pv[tt].y);
                dv[2] = f2tf32(pv[tt].z); dv[3] = f2tf32(pv[tt].w);
            }
        }

        // O += P @ V ; A-frag from P C-frags via shuffle, Vcur read = free V^T
        #pragma unroll
        for (int ks = 0; ks < 16; ks++) {
            uint32_t x0, x1;
            x0 = __shfl_sync(0xffffffffu, __float_as_uint(s[ks][0]), src1);
            x1 = __shfl_sync(0xffffffffu, __float_as_uint(s[ks][1]), src1);
            uint32_t a0 = sel ? x1 : x0;
            x0 = __shfl_sync(0xffffffffu, __float_as_uint(s[ks][2]), src1);
            x1 = __shfl_sync(0xffffffffu, __float_as_uint(s[ks][3]), src1);
            uint32_t a1 = sel ? x1 : x0;
            x0 = __shfl_sync(0xffffffffu, __float_as_uint(s[ks][0]), src2);
            x1 = __shfl_sync(0xffffffffu, __float_as_uint(s[ks][1]), src2);
            uint32_t a2 = sel ? x1 : x0;
            x0 = __shfl_sync(0xffffffffu, __float_as_uint(s[ks][2]), src2);
            x1 = __shfl_sync(0xffffffffu, __float_as_uint(s[ks][3]), src2);
            uint32_t a3 = sel ? x1 : x0;
            #pragma unroll
            for (int nt = 0; nt < 8; nt++) {
                uint32_t b0 = Vcur[(ks * 8 + t)     * ATT_STR + nt * 8 + g];
                uint32_t b1 = Vcur[(ks * 8 + t + 4) * ATT_STR + nt * 8 + g];
                mma_tf32(o[nt], a0, a1, a2, a3, b0, b1);
            }
        }
    }

    // epilogue: normalize, write [B,S,D]
    const float invA = 1.0f / lA;
    const float invB = 1.0f / lB;
    float* OrA = Out + (size_t)(b * SEQ + rowA) * DMODEL + h * DH;
    float* OrB = Out + (size_t)(b * SEQ + rowB) * DMODEL + h * DH;
    #pragma unroll
    for (int nt = 0; nt < 8; nt++) {
        const int c = nt * 8 + 2 * t;
        *(float2*)(OrA + c) = make_float2(o[nt][0] * invA, o[nt][1] * invA);
        *(float2*)(OrB + c) = make_float2(o[nt][2] * invB, o[nt][3] * invB);
    }
}

// ---------------------------------------------------------------------------
extern "C" void kernel_launch(void* const* d_in, const int* in_sizes, int n_in,
                              void* d_out, int out_size)
{
    (void)in_sizes; (void)n_in; (void)out_size;
    const float* x     = (const float*)d_in[0];
    const float* w_in  = (const float*)d_in[1];
    const float* b_in  = (const float*)d_in[2];
    const float* w_out = (const float*)d_in[3];
    const float* b_out = (const float*)d_in[4];
    const int*   cmask = (const int*)  d_in[5];
    float* out = (float*)d_out;

    float *qkv, *att;
    cudaGetSymbolAddress((void**)&qkv, g_qkv);
    cudaGetSymbolAddress((void**)&att, g_att);

    cudaFuncSetAttribute(flash_attn_tc,
                         cudaFuncAttributeMaxDynamicSharedMemorySize, ATT_SMEM);

    // 1) qkv = x @ w_in^T + b_in   (single-pass tf32)
    gemm_mma<<<dim3(THREE_D / TILE_N, MROWS / TILE_M), 256>>>(
        x, w_in, b_in, qkv, MROWS, THREE_D, DMODEL);

    // 2) flash attention on tensor pipe -> att [B,S,D]
    flash_attn_tc<<<dim3(SEQ / 128, BATCH * NHEADS), 256, ATT_SMEM>>>(
        qkv, cmask, att);

    // 3) out = att @ w_out^T + b_out  (single-pass tf32)
    gemm_mma<<<dim3(DMODEL / TILE_N, MROWS / TILE_M), 256>>>(
        att, w_out, b_out, out, MROWS, DMODEL, DMODEL);
}

// round 7
// speedup vs baseline: 2.5353x; 1.2134x over previous
#include <cuda_runtime.h>
#include <cstdint>

// ---------------- problem constants ----------------
#define BATCH   2
#define SEQ     2048
#define DMODEL  512
#define NHEADS  8
#define DH      64
#define MROWS   (BATCH*SEQ)      // 4096
#define THREE_D (3*DMODEL)       // 1536

// scratch (no cudaMalloc allowed)
__device__ float g_qkv[(size_t)MROWS * THREE_D];   // 25.2 MB
__device__ float g_att[(size_t)MROWS * DMODEL];    //  8.4 MB

// ---------------------------------------------------------------------------
// helpers
// ---------------------------------------------------------------------------
__device__ __forceinline__ uint32_t f2tf32(float f) {
    uint32_t r;
    asm("cvt.rna.tf32.f32 %0, %1;" : "=r"(r) : "f"(f));
    return r;
}

__device__ __forceinline__ void mma_tf32(float c[4], uint32_t a0, uint32_t a1,
                                         uint32_t a2, uint32_t a3,
                                         uint32_t b0, uint32_t b1) {
    asm volatile(
        "mma.sync.aligned.m16n8k8.row.col.f32.tf32.tf32.f32 "
        "{%0,%1,%2,%3}, {%4,%5,%6,%7}, {%8,%9}, {%0,%1,%2,%3};"
        : "+f"(c[0]), "+f"(c[1]), "+f"(c[2]), "+f"(c[3])
        : "r"(a0), "r"(a1), "r"(a2), "r"(a3), "r"(b0), "r"(b1));
}

__device__ __forceinline__ void cp_async16(uint32_t smem_addr, const void* gptr) {
    asm volatile("cp.async.cg.shared.global [%0], [%1], 16;"
                 :: "r"(smem_addr), "l"(gptr) : "memory");
}
__device__ __forceinline__ void cp_async_commit() {
    asm volatile("cp.async.commit_group;" ::: "memory");
}
__device__ __forceinline__ void cp_async_wait0() {
    asm volatile("cp.async.wait_group 0;" ::: "memory");
}

// ===========================================================================
// Single-pass TF32 mma.sync GEMM: C = A @ B^T + bias (validated R3 version).
// A, B row-major NT. CTA tile 128x128, stage K=16, 8 warps (4x2).
// ===========================================================================
#define TILE_M  128
#define TILE_N  128
#define STAGE_K 16
#define LDS_STR 20

__global__ __launch_bounds__(256, 2)
void gemm_mma(const float* __restrict__ A, const float* __restrict__ B,
              const float* __restrict__ bias, float* __restrict__ C,
              int M, int N, int K)
{
    __shared__ uint32_t As[TILE_M * LDS_STR];
    __shared__ uint32_t Bs[TILE_N * LDS_STR];

    const int tid = threadIdx.x;
    const int wid = tid >> 5;
    const int lane = tid & 31;
    const int g   = lane >> 2;
    const int t   = lane & 3;
    const int wm  = wid >> 1;
    const int wn  = wid & 1;
    const int bm  = blockIdx.y * TILE_M;
    const int bn  = blockIdx.x * TILE_N;

    const float* Ab = A + (size_t)bm * K;
    const float* Bb = B + (size_t)bn * K;

    const int row0 = tid >> 2;
    const int kq0  = (tid & 3) << 2;
    const int row1 = (tid + 256) >> 2;
    const int kq1  = ((tid + 256) & 3) << 2;

    float acc[2][8][4] = {};
    float4 pa0, pa1, pb0, pb1;

    pa0 = *(const float4*)(Ab + (size_t)row0 * K + kq0);
    pa1 = *(const float4*)(Ab + (size_t)row1 * K + kq1);
    pb0 = *(const float4*)(Bb + (size_t)row0 * K + kq0);
    pb1 = *(const float4*)(Bb + (size_t)row1 * K + kq1);
    {
        uint32_t* d = &As[row0 * LDS_STR + kq0];
        d[0]=f2tf32(pa0.x); d[1]=f2tf32(pa0.y); d[2]=f2tf32(pa0.z); d[3]=f2tf32(pa0.w);
        d = &As[row1 * LDS_STR + kq1];
        d[0]=f2tf32(pa1.x); d[1]=f2tf32(pa1.y); d[2]=f2tf32(pa1.z); d[3]=f2tf32(pa1.w);
        d = &Bs[row0 * LDS_STR + kq0];
        d[0]=f2tf32(pb0.x); d[1]=f2tf32(pb0.y); d[2]=f2tf32(pb0.z); d[3]=f2tf32(pb0.w);
        d = &Bs[row1 * LDS_STR + kq1];
        d[0]=f2tf32(pb1.x); d[1]=f2tf32(pb1.y); d[2]=f2tf32(pb1.z); d[3]=f2tf32(pb1.w);
    }
    __syncthreads();

    const int NS = K / STAGE_K;
    for (int s = 0; s < NS; s++) {
        if (s + 1 < NS) {
            const int k0 = (s + 1) * STAGE_K;
            pa0 = *(const float4*)(Ab + (size_t)row0 * K + k0 + kq0);
            pa1 = *(const float4*)(Ab + (size_t)row1 * K + k0 + kq1);
            pb0 = *(const float4*)(Bb + (size_t)row0 * K + k0 + kq0);
            pb1 = *(const float4*)(Bb + (size_t)row1 * K + k0 + kq1);
        }

        #pragma unroll
        for (int ks = 0; ks < 2; ks++) {
            const int k0 = ks * 8;
            uint32_t a[2][4];
            #pragma unroll
            for (int mt = 0; mt < 2; mt++) {
                const int m0 = wm * 32 + mt * 16;
                a[mt][0] = As[(m0 + g)     * LDS_STR + k0 + t];
                a[mt][1] = As[(m0 + 8 + g) * LDS_STR + k0 + t];
                a[mt][2] = As[(m0 + g)     * LDS_STR + k0 + t + 4];
                a[mt][3] = As[(m0 + 8 + g) * LDS_STR + k0 + t + 4];
            }
            #pragma unroll
            for (int nt = 0; nt < 8; nt++) {
                const int n0 = wn * 64 + nt * 8;
                uint32_t b0 = Bs[(n0 + g) * LDS_STR + k0 + t];
                uint32_t b1 = Bs[(n0 + g) * LDS_STR + k0 + t + 4];
                mma_tf32(acc[0][nt], a[0][0], a[0][1], a[0][2], a[0][3], b0, b1);
                mma_tf32(acc[1][nt], a[1][0], a[1][1], a[1][2], a[1][3], b0, b1);
            }
        }
        __syncthreads();

        if (s + 1 < NS) {
            uint32_t* d = &As[row0 * LDS_STR + kq0];
            d[0]=f2tf32(pa0.x); d[1]=f2tf32(pa0.y); d[2]=f2tf32(pa0.z); d[3]=f2tf32(pa0.w);
            d = &As[row1 * LDS_STR + kq1];
            d[0]=f2tf32(pa1.x); d[1]=f2tf32(pa1.y); d[2]=f2tf32(pa1.z); d[3]=f2tf32(pa1.w);
            d = &Bs[row0 * LDS_STR + kq0];
            d[0]=f2tf32(pb0.x); d[1]=f2tf32(pb0.y); d[2]=f2tf32(pb0.z); d[3]=f2tf32(pb0.w);
            d = &Bs[row1 * LDS_STR + kq1];
            d[0]=f2tf32(pb1.x); d[1]=f2tf32(pb1.y); d[2]=f2tf32(pb1.z); d[3]=f2tf32(pb1.w);
            __syncthreads();
        }
    }

    #pragma unroll
    for (int mt = 0; mt < 2; mt++) {
        const int r0 = bm + wm * 32 + mt * 16 + g;
        #pragma unroll
        for (int nt = 0; nt < 8; nt++) {
            const int c0 = bn + wn * 64 + nt * 8 + t * 2;
            float2 bv = *(const float2*)(bias + c0);
            float2 lo = make_float2(acc[mt][nt][0] + bv.x, acc[mt][nt][1] + bv.y);
            float2 hi = make_float2(acc[mt][nt][2] + bv.x, acc[mt][nt][3] + bv.y);
            *(float2*)(C + (size_t)r0 * N + c0)       = lo;
            *(float2*)(C + (size_t)(r0 + 8) * N + c0) = hi;
        }
    }
}

// ===========================================================================
// Flash attention on tensor pipe (tf32), cp.async-pipelined K/V.
// qkv: [4096,1536] chunk order q|v|k. Q tile 128 rows, K tile 128 keys.
// 8 warps, warp w owns q rows [16w,16w+16).
// Smem (174080B): Qs, Ks, Vs (tf32) + rawK, rawV (fp32 cp.async staging).
// Pipeline: raw holds tile kt+1 in flight while tf32 holds tile kt.
// Per-thread same-region mapping makes raw reuse safe (thread reads its
// region in convert, then issues its own cp.async overwriting that region).
// ===========================================================================
#define ATT_STR  68
#define ATT_TILE (128 * ATT_STR)
#define ATT_SMEM (5 * ATT_TILE * 4)   // 174080

__global__ __launch_bounds__(256)
void flash_attn_tc(const float* __restrict__ qkv,
                   const int*   __restrict__ cmask,
                   float* __restrict__ Out)
{
    extern __shared__ uint32_t sm[];
    uint32_t* Qs   = sm;
    uint32_t* Ks   = sm + ATT_TILE;
    uint32_t* Vs   = sm + 2 * ATT_TILE;
    float*    rawK = (float*)(sm + 3 * ATT_TILE);
    float*    rawV = (float*)(sm + 4 * ATT_TILE);

    const int tid  = threadIdx.x;
    const int wid  = tid >> 5;
    const int lane = tid & 31;
    const int g    = lane >> 2;
    const int t    = lane & 3;
    const int qt   = (SEQ / 128 - 1) - blockIdx.x;   // descending: LPT schedule
    const int bh   = blockIdx.y;
    const int b    = bh >> 3;
    const int h    = bh & 7;
    const int causal = cmask[0];

    const float* base = qkv + (size_t)(b * SEQ) * THREE_D + h * DH;
    const float* Qg = base;               // q chunk
    const float* Vg = base + DMODEL;      // v chunk (q|v|k quirk)
    const float* Kg = base + 2 * DMODEL;  // k chunk

    const int q0  = qt * 128;
    const int lr  = tid >> 4;             // load row base 0..15 (tt steps +16)
    const int lc4 = (tid & 15) * 4;       // load col (x4)

    const uint32_t rawK_s = (uint32_t)__cvta_generic_to_shared(rawK);
    const uint32_t rawV_s = (uint32_t)__cvta_generic_to_shared(rawV);

    // prologue: cp.async tile 0 into raw staging; load+convert Q meanwhile
    #pragma unroll
    for (int tt = 0; tt < 8; tt++) {
        const int r = lr + tt * 16;
        cp_async16(rawK_s + (r * ATT_STR + lc4) * 4, Kg + (size_t)r * THREE_D + lc4);
        cp_async16(rawV_s + (r * ATT_STR + lc4) * 4, Vg + (size_t)r * THREE_D + lc4);
    }
    cp_async_commit();

    #pragma unroll
    for (int tt = 0; tt < 8; tt++) {
        const int r = lr + tt * 16;
        float4 v = *(const float4*)(Qg + (size_t)(q0 + r) * THREE_D + lc4);
        uint32_t* d = &Qs[r * ATT_STR + lc4];
        d[0] = f2tf32(v.x * 0.125f); d[1] = f2tf32(v.y * 0.125f);
        d[2] = f2tf32(v.z * 0.125f); d[3] = f2tf32(v.w * 0.125f);
    }

    float o[8][4] = {};
    float mA = -1e30f, mB = -1e30f, lA = 0.f, lB = 0.f;
    const int m0   = wid * 16;
    const int rowA = q0 + m0 + g;
    const int rowB = rowA + 8;
    const int src1 = g * 4 + (t >> 1);
    const int src2 = src1 + 2;
    const int sel  = t & 1;

    const int NKT = causal ? (qt + 1) : (SEQ / 128);
    for (int kt = 0; kt < NKT; kt++) {
        cp_async_wait0();          // raw tile kt landed
        __syncthreads();           // + all warps done reading Ks/Vs (iter kt-1)

        // convert raw -> tf32 (smem to smem, no long-scoreboard)
        #pragma unroll
        for (int tt = 0; tt < 8; tt++) {
            const int r   = lr + tt * 16;
            const int off = r * ATT_STR + lc4;
            float4 kv = *(const float4*)(rawK + off);
            uint32_t* dk = &Ks[off];
            dk[0] = f2tf32(kv.x); dk[1] = f2tf32(kv.y);
            dk[2] = f2tf32(kv.z); dk[3] = f2tf32(kv.w);
            float4 vv = *(const float4*)(rawV + off);
            uint32_t* dv = &Vs[off];
            dv[0] = f2tf32(vv.x); dv[1] = f2tf32(vv.y);
            dv[2] = f2tf32(vv.z); dv[3] = f2tf32(vv.w);
        }

        // kick off next tile into raw (this thread already read its region)
        if (kt + 1 < NKT) {
            const int kn = (kt + 1) * 128;
            #pragma unroll
            for (int tt = 0; tt < 8; tt++) {
                const int r = lr + tt * 16;
                cp_async16(rawK_s + (r * ATT_STR + lc4) * 4,
                           Kg + (size_t)(kn + r) * THREE_D + lc4);
                cp_async16(rawV_s + (r * ATT_STR + lc4) * 4,
                           Vg + (size_t)(kn + r) * THREE_D + lc4);
            }
            cp_async_commit();
        }
        __syncthreads();           // tf32 tiles ready for all warps

        // S = (Q*scale) @ K^T : 16 rows x 128 cols per warp
        float s[16][4];
        #pragma unroll
        for (int nt = 0; nt < 16; nt++)
            s[nt][0] = s[nt][1] = s[nt][2] = s[nt][3] = 0.f;
        #pragma unroll
        for (int ks = 0; ks < 8; ks++) {
            const int k8 = ks * 8;
            uint32_t a0 = Qs[(m0 + g)     * ATT_STR + k8 + t];
            uint32_t a1 = Qs[(m0 + 8 + g) * ATT_STR + k8 + t];
            uint32_t a2 = Qs[(m0 + g)     * ATT_STR + k8 + t + 4];
            uint32_t a3 = Qs[(m0 + 8 + g) * ATT_STR + k8 + t + 4];
            #pragma unroll
            for (int nt = 0; nt < 16; nt++) {
                uint32_t b0 = Ks[(nt * 8 + g) * ATT_STR + k8 + t];
                uint32_t b1 = Ks[(nt * 8 + g) * ATT_STR + k8 + t + 4];
                mma_tf32(s[nt], a0, a1, a2, a3, b0, b1);
            }
        }

        // causal mask (diagonal tile only)
        if (causal && kt == qt) {
            const int k0 = kt * 128;
            #pragma unroll
            for (int nt = 0; nt < 16; nt++) {
                const int c = k0 + nt * 8 + 2 * t;
                if (c     > rowA) s[nt][0] = -1e30f;
                if (c + 1 > rowA) s[nt][1] = -1e30f;
                if (c     > rowB) s[nt][2] = -1e30f;
                if (c + 1 > rowB) s[nt][3] = -1e30f;
            }
        }

        // online softmax (rows rA, rB; reduce over t-quad)
        float mxA = -1e30f, mxB = -1e30f;
        #pragma unroll
        for (int nt = 0; nt < 16; nt++) {
            mxA = fmaxf(mxA, fmaxf(s[nt][0], s[nt][1]));
            mxB = fmaxf(mxB, fmaxf(s[nt][2], s[nt][3]));
        }
        mxA = fmaxf(mxA, __shfl_xor_sync(0xffffffffu, mxA, 1));
        mxA = fmaxf(mxA, __shfl_xor_sync(0xffffffffu, mxA, 2));
        mxB = fmaxf(mxB, __shfl_xor_sync(0xffffffffu, mxB, 1));
        mxB = fmaxf(mxB, __shfl_xor_sync(0xffffffffu, mxB, 2));
        const float mnA = fmaxf(mA, mxA);
        const float mnB = fmaxf(mB, mxB);
        const float corrA = __expf(mA - mnA);
        const float corrB = __expf(mB - mnB);
        mA = mnA; mB = mnB;

        float sumA = 0.f, sumB = 0.f;
        #pragma unroll
        for (int nt = 0; nt < 16; nt++) {
            float p0 = __expf(s[nt][0] - mnA);
            float p1 = __expf(s[nt][1] - mnA);
            float p2 = __expf(s[nt][2] - mnB);
            float p3 = __expf(s[nt][3] - mnB);
            sumA += p0 + p1;
            sumB += p2 + p3;
            s[nt][0] = __uint_as_float(f2tf32(p0));
            s[nt][1] = __uint_as_float(f2tf32(p1));
            s[nt][2] = __uint_as_float(f2tf32(p2));
            s[nt][3] = __uint_as_float(f2tf32(p3));
        }
        sumA += __shfl_xor_sync(0xffffffffu, sumA, 1);
        sumA += __shfl_xor_sync(0xffffffffu, sumA, 2);
        sumB += __shfl_xor_sync(0xffffffffu, sumB, 1);
        sumB += __shfl_xor_sync(0xffffffffu, sumB, 2);
        lA = lA * corrA + sumA;
        lB = lB * corrB + sumB;
        #pragma unroll
        for (int nt = 0; nt < 8; nt++) {
            o[nt][0] *= corrA; o[nt][1] *= corrA;
            o[nt][2] *= corrB; o[nt][3] *= corrB;
        }

        // O += P @ V ; A-frag from P C-frags via shuffle, Vs read = free V^T
        #pragma unroll
        for (int ks = 0; ks < 16; ks++) {
            uint32_t x0, x1;
            x0 = __shfl_sync(0xffffffffu, __float_as_uint(s[ks][0]), src1);
            x1 = __shfl_sync(0xffffffffu, __float_as_uint(s[ks][1]), src1);
            uint32_t a0 = sel ? x1 : x0;
            x0 = __shfl_sync(0xffffffffu, __float_as_uint(s[ks][2]), src1);
            x1 = __shfl_sync(0xffffffffu, __float_as_uint(s[ks][3]), src1);
            uint32_t a1 = sel ? x1 : x0;
            x0 = __shfl_sync(0xffffffffu, __float_as_uint(s[ks][0]), src2);
            x1 = __shfl_sync(0xffffffffu, __float_as_uint(s[ks][1]), src2);
            uint32_t a2 = sel ? x1 : x0;
            x0 = __shfl_sync(0xffffffffu, __float_as_uint(s[ks][2]), src2);
            x1 = __shfl_sync(0xffffffffu, __float_as_uint(s[ks][3]), src2);
            uint32_t a3 = sel ? x1 : x0;
            #pragma unroll
            for (int nt = 0; nt < 8; nt++) {
                uint32_t b0 = Vs[(ks * 8 + t)     * ATT_STR + nt * 8 + g];
                uint32_t b1 = Vs[(ks * 8 + t + 4) * ATT_STR + nt * 8 + g];
                mma_tf32(o[nt], a0, a1, a2, a3, b0, b1);
            }
        }
    }

    // epilogue: normalize, write [B,S,D]
    const float invA = 1.0f / lA;
    const float invB = 1.0f / lB;
    float* OrA = Out + (size_t)(b * SEQ + rowA) * DMODEL + h * DH;
    float* OrB = Out + (size_t)(b * SEQ + rowB) * DMODEL + h * DH;
    #pragma unroll
    for (int nt = 0; nt < 8; nt++) {
        const int c = nt * 8 + 2 * t;
        *(float2*)(OrA + c) = make_float2(o[nt][0] * invA, o[nt][1] * invA);
        *(float2*)(OrB + c) = make_float2(o[nt][2] * invB, o[nt][3] * invB);
    }
}

// ---------------------------------------------------------------------------
extern "C" void kernel_launch(void* const* d_in, const int* in_sizes, int n_in,
                              void* d_out, int out_size)
{
    (void)in_sizes; (void)n_in; (void)out_size;
    const float* x     = (const float*)d_in[0];
    const float* w_in  = (const float*)d_in[1];
    const float* b_in  = (const float*)d_in[2];
    const float* w_out = (const float*)d_in[3];
    const float* b_out = (const float*)d_in[4];
    const int*   cmask = (const int*)  d_in[5];
    float* out = (float*)d_out;

    float *qkv, *att;
    cudaGetSymbolAddress((void**)&qkv, g_qkv);
    cudaGetSymbolAddress((void**)&att, g_att);

    cudaFuncSetAttribute(flash_attn_tc,
                         cudaFuncAttributeMaxDynamicSharedMemorySize, ATT_SMEM);

    // 1) qkv = x @ w_in^T + b_in   (single-pass tf32)
    gemm_mma<<<dim3(THREE_D / TILE_N, MROWS / TILE_M), 256>>>(
        x, w_in, b_in, qkv, MROWS, THREE_D, DMODEL);

    // 2) flash attention on tensor pipe -> att [B,S,D]
    flash_attn_tc<<<dim3(SEQ / 128, BATCH * NHEADS), 256, ATT_SMEM>>>(
        qkv, cmask, att);

    // 3) out = att @ w_out^T + b_out  (single-pass tf32)
    gemm_mma<<<dim3(DMODEL / TILE_N, MROWS / TILE_M), 256>>>(
        att, w_out, b_out, out, MROWS, DMODEL, DMODEL);
}